// round 9
// baseline (speedup 1.0000x reference)
#include <cuda_runtime.h>
#include <cuda_fp16.h>

#define E_DIM   1024
#define M_TOT   4096
#define SEQ     2048
#define NBATCH  32
#define HD      64

// scratch
__device__ __half g_xh[M_TOT * E_DIM];
__device__ __half g_Wh[3 * E_DIM * E_DIM];    // Wq | Wk | Wv stacked [3072,1024]
__device__ __half g_Kh[M_TOT * E_DIM];
__device__ __half g_Vh[M_TOT * E_DIM];
__device__ float  g_Tp[NBATCH * 4 * HD * HD]; // partial K^T V per (n, chunk)
__device__ __half g_Th[NBATCH * HD * HD];     // T[n] = 0.125 * K^T V (f16)

__device__ __forceinline__ unsigned su32(const void* p) {
    return (unsigned)__cvta_generic_to_shared(p);
}
#define CPA16(d, s) \
    asm volatile("cp.async.cg.shared.global [%0],[%1],16;" :: "r"(d), "l"(s))
#define CP_COMMIT() asm volatile("cp.async.commit_group;")
#define CP_WAIT(n)  asm volatile("cp.async.wait_group %0;" :: "n"(n))

#define LDSM_X4(r0, r1, r2, r3, p) \
    asm volatile("ldmatrix.sync.aligned.m8n8.x4.shared.b16 {%0,%1,%2,%3},[%4];" \
                 : "=r"(r0), "=r"(r1), "=r"(r2), "=r"(r3) : "r"(p))
#define LDSM_X4T(r0, r1, r2, r3, p) \
    asm volatile("ldmatrix.sync.aligned.m8n8.x4.trans.shared.b16 {%0,%1,%2,%3},[%4];" \
                 : "=r"(r0), "=r"(r1), "=r"(r2), "=r"(r3) : "r"(p))

#define MMA16(c, a, b0_, b1_) \
    asm volatile("mma.sync.aligned.m16n8k16.row.col.f32.f16.f16.f32 " \
                 "{%0,%1,%2,%3},{%4,%5,%6,%7},{%8,%9},{%0,%1,%2,%3};" \
                 : "+f"((c)[0]), "+f"((c)[1]), "+f"((c)[2]), "+f"((c)[3]) \
                 : "r"((a)[0]), "r"((a)[1]), "r"((a)[2]), "r"((a)[3]), \
                   "r"(b0_), "r"(b1_))

// ---------------------------------------------------------------------------
// cvt: f32 -> f16 for x, Wq, Wk, Wv. Exactly one float4 per thread.
// ---------------------------------------------------------------------------
#define CVT_NX ((M_TOT * E_DIM) / 4)
#define CVT_NW ((E_DIM * E_DIM) / 4)
#define CVT_TOT (CVT_NX + 3 * CVT_NW)

__global__ void cvt_kernel(const float* __restrict__ x,
                           const float* __restrict__ wq,
                           const float* __restrict__ wk,
                           const float* __restrict__ wv)
{
    int i = blockIdx.x * 256 + threadIdx.x;
    if (i >= CVT_TOT) return;
    const float* s; __half* d; int off;
    if (i < CVT_NX)                   { s = x;  d = g_xh;                     off = i; }
    else if (i < CVT_NX + CVT_NW)     { s = wq; d = g_Wh;                     off = i - CVT_NX; }
    else if (i < CVT_NX + 2 * CVT_NW) { s = wk; d = g_Wh + E_DIM * E_DIM;     off = i - CVT_NX - CVT_NW; }
    else                              { s = wv; d = g_Wh + 2 * E_DIM * E_DIM; off = i - CVT_NX - 2 * CVT_NW; }
    float4 v = ((const float4*)s)[off];
    ((__half2*)d)[2 * off]     = __floats2half2_rn(v.x, v.y);
    ((__half2*)d)[2 * off + 1] = __floats2half2_rn(v.z, v.w);
}

// ---------------------------------------------------------------------------
// proj_kv: C[4096,2048] = X @ [Wk;Wv]^T + bias  -> g_Kh / g_Vh (f16)
// CTA 128x128, BK=64, 3-stage cp.async, 8 warps (2x4). grid (16, 32).
// ---------------------------------------------------------------------------
#define PJ_LD   72
#define PJ_STG  ((128 + 128) * PJ_LD)
#define PJ_SMEM (3 * PJ_STG * (int)sizeof(__half))   // 110592 B

__global__ __launch_bounds__(256, 2) void proj_kv_kernel(
    const float* __restrict__ bk, const float* __restrict__ bv)
{
    extern __shared__ __half sh[];

    const int tid  = threadIdx.x, lane = tid & 31;
    const int warp = tid >> 5, warpM = warp >> 2, warpN = warp & 3;
    const int g = lane >> 2, tg = lane & 3;
    const int quad = lane >> 3, rr = lane & 7;
    const int m0 = blockIdx.y * 128;
    const int n0 = blockIdx.x * 128;      // 0..2047 over Wk|Wv

    float acc[4][4][4];
#pragma unroll
    for (int i = 0; i < 4; i++)
#pragma unroll
        for (int j = 0; j < 4; j++)
#pragma unroll
            for (int f = 0; f < 4; f++) acc[i][j][f] = 0.f;

#define PJ_FILL(st, k0, WROW0)                                                \
    do {                                                                      \
        __half* Xs = sh + (st) * PJ_STG;                                      \
        __half* Ws = Xs + 128 * PJ_LD;                                        \
        _Pragma("unroll")                                                     \
        for (int t = 0; t < 4; t++) {                                         \
            int seg = tid + t * 256;                                          \
            int row = seg >> 3, c16 = seg & 7;                                \
            CPA16(su32(Xs + row * PJ_LD + c16 * 8),                           \
                  &g_xh[(size_t)(m0 + row) * E_DIM + (k0) + c16 * 8]);        \
        }                                                                     \
        _Pragma("unroll")                                                     \
        for (int t = 0; t < 4; t++) {                                         \
            int seg = tid + t * 256;                                          \
            int row = seg >> 3, c16 = seg & 7;                                \
            CPA16(su32(Ws + row * PJ_LD + c16 * 8),                           \
                  &g_Wh[(size_t)((WROW0) + row) * E_DIM + (k0) + c16 * 8]);   \
        }                                                                     \
        CP_COMMIT();                                                          \
    } while (0)

    PJ_FILL(0, 0,  E_DIM + n0);
    PJ_FILL(1, 64, E_DIM + n0);

    const int NKT = E_DIM / 64;
    for (int kt = 0; kt < NKT; kt++) {
        const int st = kt % 3;
        if (kt < NKT - 1) { CP_WAIT(1); } else { CP_WAIT(0); }
        __syncthreads();

        const __half* Xs = sh + st * PJ_STG;
        const __half* Ws = Xs + 128 * PJ_LD;

#pragma unroll
        for (int ks = 0; ks < 4; ks++) {
            const int kb = ks * 16;
            unsigned a[4][4];
#pragma unroll
            for (int i = 0; i < 4; i++) {
                int row = warpM * 64 + i * 16 + ((quad & 1) << 3) + rr;
                int col = kb + ((quad >> 1) << 3);
                LDSM_X4(a[i][0], a[i][1], a[i][2], a[i][3],
                        su32(Xs + row * PJ_LD + col));
            }
#pragma unroll
            for (int jj = 0; jj < 2; jj++) {
                int nrow = warpN * 32 + jj * 16 + ((quad >> 1) << 3) + rr;
                int col  = kb + ((quad & 1) << 3);
                unsigned b0, b1, b2, b3;
                LDSM_X4(b0, b1, b2, b3, su32(Ws + nrow * PJ_LD + col));
#pragma unroll
                for (int i = 0; i < 4; i++) {
                    MMA16(acc[i][2 * jj],     a[i], b0, b1);
                    MMA16(acc[i][2 * jj + 1], a[i], b2, b3);
                }
            }
        }

        if (kt + 2 < NKT) PJ_FILL((kt + 2) % 3, (kt + 2) * 64, E_DIM + n0);
    }

    const int which = n0 >> 10;           // 0 -> K, 1 -> V
    const int nbase = n0 & 1023;
    const float* bias = which ? bv : bk;
    __half* C = which ? g_Vh : g_Kh;

#pragma unroll
    for (int j = 0; j < 4; j++) {
        int col = nbase + warpN * 32 + j * 8 + tg * 2;
        float b0 = bias[col], b1 = bias[col + 1];
#pragma unroll
        for (int i = 0; i < 4; i++) {
            int rbase = m0 + warpM * 64 + i * 16;
            *(__half2*)&C[(size_t)(rbase + g) * E_DIM + col] =
                __floats2half2_rn(acc[i][j][0] + b0, acc[i][j][1] + b1);
            *(__half2*)&C[(size_t)(rbase + g + 8) * E_DIM + col] =
                __floats2half2_rn(acc[i][j][2] + b0, acc[i][j][3] + b1);
        }
    }
}

// ---------------------------------------------------------------------------
// kv_kernel: partial T[n,ch] = K[n, ch*512:+512]^T @ V[same]  (f32)
// grid (4, 32). Scale 0.125 deferred to red_kernel.
// ---------------------------------------------------------------------------
#define KV_LD 72

__global__ __launch_bounds__(256) void kv_kernel()
{
    const int ch = blockIdx.x;
    const int b  = blockIdx.y;
    const __half* Kg = g_Kh + (size_t)b * SEQ * HD + (size_t)ch * 512 * HD;
    const __half* Vg = g_Vh + (size_t)b * SEQ * HD + (size_t)ch * 512 * HD;

    __shared__ __half Ks[2][64 * KV_LD];
    __shared__ __half Vs[2][64 * KV_LD];

    const int tid  = threadIdx.x, lane = tid & 31, warp = tid >> 5;
    const int g = lane >> 2, tg = lane & 3;
    const int quad = lane >> 3, rr = lane & 7;
    const int mh = (warp >> 2) * 32;
    const int nb = (warp & 3) * 16;

    float accT[2][2][4];
#pragma unroll
    for (int mt = 0; mt < 2; mt++)
#pragma unroll
        for (int jn = 0; jn < 2; jn++)
#pragma unroll
            for (int f = 0; f < 4; f++) accT[mt][jn][f] = 0.f;

#define KV2_ISSUE(buf, k0)                                                    \
    do {                                                                      \
        _Pragma("unroll")                                                     \
        for (int t = 0; t < 2; t++) {                                         \
            int seg = tid + t * 256;                                          \
            int row = seg >> 3, s8 = seg & 7;                                 \
            CPA16(su32(&Ks[buf][row * KV_LD + s8 * 8]),                       \
                  &Kg[(size_t)((k0) + row) * HD + s8 * 8]);                   \
            CPA16(su32(&Vs[buf][row * KV_LD + s8 * 8]),                       \
                  &Vg[(size_t)((k0) + row) * HD + s8 * 8]);                   \
        }                                                                     \
        CP_COMMIT();                                                          \
    } while (0)

    KV2_ISSUE(0, 0);

    for (int c = 0; c < 8; c++) {
        int buf = c & 1;
        __syncthreads();
        if (c < 7) { KV2_ISSUE(buf ^ 1, (c + 1) * 64); CP_WAIT(1); }
        else       { CP_WAIT(0); }
        __syncthreads();

#pragma unroll
        for (int ks = 0; ks < 4; ks++) {
            const int sb = ks * 16;
            unsigned a[2][4];
#pragma unroll
            for (int mt = 0; mt < 2; mt++) {
                int row = sb + ((quad >> 1) << 3) + rr;
                int col = mh + mt * 16 + ((quad & 1) << 3);
                LDSM_X4T(a[mt][0], a[mt][1], a[mt][2], a[mt][3],
                         su32(&Ks[buf][row * KV_LD + col]));
            }
            int vrow = sb + ((quad & 1) << 3) + rr;
            int vcol = nb + ((quad >> 1) << 3);
            unsigned v0, v1, v2, v3;
            LDSM_X4T(v0, v1, v2, v3, su32(&Vs[buf][vrow * KV_LD + vcol]));
#pragma unroll
            for (int mt = 0; mt < 2; mt++) {
                MMA16(accT[mt][0], a[mt], v0, v1);
                MMA16(accT[mt][1], a[mt], v2, v3);
            }
        }
    }

    float* Tp = g_Tp + ((size_t)(b * 4 + ch)) * HD * HD;
#pragma unroll
    for (int mt = 0; mt < 2; mt++) {
        int dk0 = mh + mt * 16;
#pragma unroll
        for (int jn = 0; jn < 2; jn++) {
            int dv = nb + jn * 8 + tg * 2;
            *(float2*)&Tp[(dk0 + g) * HD + dv] =
                make_float2(accT[mt][jn][0], accT[mt][jn][1]);
            *(float2*)&Tp[(dk0 + g + 8) * HD + dv] =
                make_float2(accT[mt][jn][2], accT[mt][jn][3]);
        }
    }
}

// ---------------------------------------------------------------------------
// red_kernel: T[n] = 0.125 * sum_ch Tp[n,ch]  -> f16 g_Th. grid 32.
// ---------------------------------------------------------------------------
__global__ __launch_bounds__(256) void red_kernel()
{
    const int n = blockIdx.x;
    const float4* P4 = (const float4*)(g_Tp + (size_t)n * 4 * HD * HD);
    __half* T = g_Th + (size_t)n * HD * HD;
    int tid = threadIdx.x;
#pragma unroll
    for (int t = 0; t < 4; t++) {
        int slot = tid + t * 256;            // 0..1023 float4 slots
        float4 p0 = P4[slot];
        float4 p1 = P4[slot + 1024];
        float4 p2 = P4[slot + 2048];
        float4 p3 = P4[slot + 3072];
        *(__half2*)&T[slot * 4] =
            __floats2half2_rn((p0.x + p1.x + p2.x + p3.x) * 0.125f,
                              (p0.y + p1.y + p2.y + p3.y) * 0.125f);
        *(__half2*)&T[slot * 4 + 2] =
            __floats2half2_rn((p0.z + p1.z + p2.z + p3.z) * 0.125f,
                              (p0.w + p1.w + p2.w + p3.w) * 0.125f);
    }
}

// ---------------------------------------------------------------------------
// proj_q: q tile = X @ Wq^T + bq (128x128, 2 heads), then FUSED epilogue:
//   out row R = 16*m + h,  out[R] = q64(m,h) @ T[n],  n = m0/128 = blockIdx.y.
// grid (8, 32). Writes f32 out directly; g_Qh never materialized.
// ---------------------------------------------------------------------------
#define QST_LD 136

__global__ __launch_bounds__(256, 2) void proj_q_kernel(
    const float* __restrict__ bq, float* __restrict__ out)
{
    extern __shared__ __half sh[];

    const int tid  = threadIdx.x, lane = tid & 31;
    const int warp = tid >> 5, warpM = warp >> 2, warpN = warp & 3;
    const int g = lane >> 2, tg = lane & 3;
    const int quad = lane >> 3, rr = lane & 7;
    const int m0 = blockIdx.y * 128;
    const int n0 = blockIdx.x * 128;      // q cols: heads h0, h0+1
    const int h0 = n0 >> 6;

    float acc[4][4][4];
#pragma unroll
    for (int i = 0; i < 4; i++)
#pragma unroll
        for (int j = 0; j < 4; j++)
#pragma unroll
            for (int f = 0; f < 4; f++) acc[i][j][f] = 0.f;

    PJ_FILL(0, 0,  n0);
    PJ_FILL(1, 64, n0);

    const int NKT = E_DIM / 64;
    for (int kt = 0; kt < NKT; kt++) {
        const int st = kt % 3;
        if (kt < NKT - 1) { CP_WAIT(1); } else { CP_WAIT(0); }
        __syncthreads();

        const __half* Xs = sh + st * PJ_STG;
        const __half* Ws = Xs + 128 * PJ_LD;

#pragma unroll
        for (int ks = 0; ks < 4; ks++) {
            const int kb = ks * 16;
            unsigned a[4][4];
#pragma unroll
            for (int i = 0; i < 4; i++) {
                int row = warpM * 64 + i * 16 + ((quad & 1) << 3) + rr;
                int col = kb + ((quad >> 1) << 3);
                LDSM_X4(a[i][0], a[i][1], a[i][2], a[i][3],
                        su32(Xs + row * PJ_LD + col));
            }
#pragma unroll
            for (int jj = 0; jj < 2; jj++) {
                int nrow = warpN * 32 + jj * 16 + ((quad >> 1) << 3) + rr;
                int col  = kb + ((quad & 1) << 3);
                unsigned b0, b1, b2, b3;
                LDSM_X4(b0, b1, b2, b3, su32(Ws + nrow * PJ_LD + col));
#pragma unroll
                for (int i = 0; i < 4; i++) {
                    MMA16(acc[i][2 * jj],     a[i], b0, b1);
                    MMA16(acc[i][2 * jj + 1], a[i], b2, b3);
                }
            }
        }

        if (kt + 2 < NKT) PJ_FILL((kt + 2) % 3, (kt + 2) * 64, n0);
    }

    // ---- Fused epilogue: stage q+bias (f16) and T[n], then out = q @ T ----
    __syncthreads();                       // all warps done reading stages
    __half* Qst = sh;                      // [128][QST_LD]
    __half* Tst = sh + 128 * QST_LD;       // [64][72]

    // T[n] via cp.async: 64 rows x 128B -> 512 chunks -> 2 per thread
#pragma unroll
    for (int t = 0; t < 2; t++) {
        int seg = tid + t * 256;
        int row = seg >> 3, c8 = seg & 7;
        CPA16(su32(Tst + row * 72 + c8 * 8),
              &g_Th[(size_t)blockIdx.y * HD * HD + row * HD + c8 * 8]);
    }
    CP_COMMIT();

    // stage q tile (+bq) to Qst
#pragma unroll
    for (int j = 0; j < 4; j++) {
        int col = warpN * 32 + j * 8 + tg * 2;          // 0..127 local
        float b0 = bq[n0 + col], b1 = bq[n0 + col + 1];
#pragma unroll
        for (int i = 0; i < 4; i++) {
            int rl = warpM * 64 + i * 16;
            *(__half2*)&Qst[(rl + g) * QST_LD + col] =
                __floats2half2_rn(acc[i][j][0] + b0, acc[i][j][1] + b1);
            *(__half2*)&Qst[(rl + g + 8) * QST_LD + col] =
                __floats2half2_rn(acc[i][j][2] + b0, acc[i][j][3] + b1);
        }
    }
    CP_WAIT(0);
    __syncthreads();

    // warp w: head hl = w>>2, rows mb = (w&3)*32 .. +32
    const int hl = warp >> 2;
    const int mb = (warp & 3) * 32;

    float accF[2][4][2][4];
#pragma unroll
    for (int i = 0; i < 2; i++)
#pragma unroll
        for (int jj = 0; jj < 4; jj++)
#pragma unroll
            for (int jn = 0; jn < 2; jn++)
#pragma unroll
                for (int f = 0; f < 4; f++) accF[i][jj][jn][f] = 0.f;

#pragma unroll
    for (int k = 0; k < 4; k++) {
        const int kb = k * 16;
        unsigned a[2][4];
#pragma unroll
        for (int i = 0; i < 2; i++) {
            int row = mb + i * 16 + ((quad & 1) << 3) + rr;
            int col = hl * 64 + kb + ((quad >> 1) << 3);
            LDSM_X4(a[i][0], a[i][1], a[i][2], a[i][3],
                    su32(Qst + row * QST_LD + col));
        }
#pragma unroll
        for (int jj = 0; jj < 4; jj++) {
            int trow = kb + ((quad & 1) << 3) + rr;
            int tcol = jj * 16 + ((quad >> 1) << 3);
            unsigned v0, v1, v2, v3;
            LDSM_X4T(v0, v1, v2, v3, su32(Tst + trow * 72 + tcol));
#pragma unroll
            for (int i = 0; i < 2; i++) {
                MMA16(accF[i][jj][0], a[i], v0, v1);
                MMA16(accF[i][jj][1], a[i], v2, v3);
            }
        }
    }

    // store: out[(16*(m0+mloc) + h0+hl)*64 + d]
#pragma unroll
    for (int i = 0; i < 2; i++) {
        int mA = m0 + mb + i * 16 + g;
        int mB = mA + 8;
        size_t RA = (size_t)(16 * mA + h0 + hl) * HD;
        size_t RB = (size_t)(16 * mB + h0 + hl) * HD;
#pragma unroll
        for (int jj = 0; jj < 4; jj++) {
#pragma unroll
            for (int jn = 0; jn < 2; jn++) {
                int d = jj * 16 + jn * 8 + tg * 2;
                *(float2*)&out[RA + d] =
                    make_float2(accF[i][jj][jn][0], accF[i][jj][jn][1]);
                *(float2*)&out[RB + d] =
                    make_float2(accF[i][jj][jn][2], accF[i][jj][jn][3]);
            }
        }
    }
}

// ---------------------------------------------------------------------------
extern "C" void kernel_launch(void* const* d_in, const int* in_sizes, int n_in,
                              void* d_out, int out_size)
{
    const float* x  = (const float*)d_in[0];
    const float* Wq = (const float*)d_in[1];
    const float* bq = (const float*)d_in[2];
    const float* Wk = (const float*)d_in[3];
    const float* bk = (const float*)d_in[4];
    const float* Wv = (const float*)d_in[5];
    const float* bv = (const float*)d_in[6];
    float* out = (float*)d_out;

    cudaFuncSetAttribute(proj_kv_kernel,
                         cudaFuncAttributeMaxDynamicSharedMemorySize, PJ_SMEM);
    cudaFuncSetAttribute(proj_q_kernel,
                         cudaFuncAttributeMaxDynamicSharedMemorySize, PJ_SMEM);

    cvt_kernel<<<CVT_TOT / 256, 256>>>(x, Wq, Wk, Wv);

    proj_kv_kernel<<<dim3(2 * E_DIM / 128, M_TOT / 128), 256, PJ_SMEM>>>(bk, bv);

    kv_kernel<<<dim3(4, NBATCH), 256>>>();

    red_kernel<<<NBATCH, 256>>>();

    proj_q_kernel<<<dim3(E_DIM / 128, M_TOT / 128), 256, PJ_SMEM>>>(bq, out);
}

// round 10
// speedup vs baseline: 1.0025x; 1.0025x over previous
#include <cuda_runtime.h>
#include <cuda_fp16.h>

#define E_DIM   1024
#define M_TOT   4096
#define SEQ     2048
#define NBATCH  32
#define HD      64

// scratch
__device__ __half g_xh[M_TOT * E_DIM];
__device__ __half g_Wh[3 * E_DIM * E_DIM];    // Wq | Wk | Wv stacked [3072,1024]
__device__ __half g_Kh[M_TOT * E_DIM];
__device__ __half g_Vh[M_TOT * E_DIM];
__device__ float  g_Tp[NBATCH * 2 * HD * HD]; // partial K^T V per (n, chunk)

__device__ __forceinline__ unsigned su32(const void* p) {
    return (unsigned)__cvta_generic_to_shared(p);
}
#define CPA16(d, s) \
    asm volatile("cp.async.cg.shared.global [%0],[%1],16;" :: "r"(d), "l"(s))
#define CP_COMMIT() asm volatile("cp.async.commit_group;")
#define CP_WAIT(n)  asm volatile("cp.async.wait_group %0;" :: "n"(n))

#define LDSM_X4(r0, r1, r2, r3, p) \
    asm volatile("ldmatrix.sync.aligned.m8n8.x4.shared.b16 {%0,%1,%2,%3},[%4];" \
                 : "=r"(r0), "=r"(r1), "=r"(r2), "=r"(r3) : "r"(p))
#define LDSM_X4T(r0, r1, r2, r3, p) \
    asm volatile("ldmatrix.sync.aligned.m8n8.x4.trans.shared.b16 {%0,%1,%2,%3},[%4];" \
                 : "=r"(r0), "=r"(r1), "=r"(r2), "=r"(r3) : "r"(p))

#define MMA16(c, a, b0_, b1_) \
    asm volatile("mma.sync.aligned.m16n8k16.row.col.f32.f16.f16.f32 " \
                 "{%0,%1,%2,%3},{%4,%5,%6,%7},{%8,%9},{%0,%1,%2,%3};" \
                 : "+f"((c)[0]), "+f"((c)[1]), "+f"((c)[2]), "+f"((c)[3]) \
                 : "r"((a)[0]), "r"((a)[1]), "r"((a)[2]), "r"((a)[3]), \
                   "r"(b0_), "r"(b1_))

// ---------------------------------------------------------------------------
// cvt: f32 -> f16 for x, Wq, Wk, Wv. Two float4 per thread (MLP=2).
// ---------------------------------------------------------------------------
#define CVT_NX ((M_TOT * E_DIM) / 4)
#define CVT_NW ((E_DIM * E_DIM) / 4)
#define CVT_TOT (CVT_NX + 3 * CVT_NW)

__device__ __forceinline__ void cvt_one(const float* __restrict__ x,
                                        const float* __restrict__ wq,
                                        const float* __restrict__ wk,
                                        const float* __restrict__ wv, int i)
{
    const float* s; __half* d; int off;
    if (i < CVT_NX)                   { s = x;  d = g_xh;                     off = i; }
    else if (i < CVT_NX + CVT_NW)     { s = wq; d = g_Wh;                     off = i - CVT_NX; }
    else if (i < CVT_NX + 2 * CVT_NW) { s = wk; d = g_Wh + E_DIM * E_DIM;     off = i - CVT_NX - CVT_NW; }
    else                              { s = wv; d = g_Wh + 2 * E_DIM * E_DIM; off = i - CVT_NX - 2 * CVT_NW; }
    float4 v = ((const float4*)s)[off];
    ((__half2*)d)[2 * off]     = __floats2half2_rn(v.x, v.y);
    ((__half2*)d)[2 * off + 1] = __floats2half2_rn(v.z, v.w);
}

__global__ void cvt_kernel(const float* __restrict__ x,
                           const float* __restrict__ wq,
                           const float* __restrict__ wk,
                           const float* __restrict__ wv)
{
    int i = (blockIdx.x * 256 + threadIdx.x) * 2;
    if (i + 1 >= CVT_TOT) { if (i < CVT_TOT) cvt_one(x, wq, wk, wv, i); return; }
    cvt_one(x, wq, wk, wv, i);
    cvt_one(x, wq, wk, wv, i + 1);
}

// ---------------------------------------------------------------------------
// proj_kv: C[4096,2048] = X @ [Wk;Wv]^T + bias  -> g_Kh / g_Vh (f16)
// CTA 128x128, BK=64, 3-stage cp.async, 8 warps (2x4). grid (16, 32).
// ---------------------------------------------------------------------------
#define PJ_LD   72
#define PJ_STG  ((128 + 128) * PJ_LD)
#define PJ_SMEM (3 * PJ_STG * (int)sizeof(__half))   // 110592 B

__global__ __launch_bounds__(256, 2) void proj_kv_kernel(
    const float* __restrict__ bk, const float* __restrict__ bv)
{
    extern __shared__ __half sh[];

    const int tid  = threadIdx.x, lane = tid & 31;
    const int warp = tid >> 5, warpM = warp >> 2, warpN = warp & 3;
    const int g = lane >> 2, tg = lane & 3;
    const int quad = lane >> 3, rr = lane & 7;
    const int m0 = blockIdx.y * 128;
    const int n0 = blockIdx.x * 128;      // 0..2047 over Wk|Wv

    float acc[4][4][4];
#pragma unroll
    for (int i = 0; i < 4; i++)
#pragma unroll
        for (int j = 0; j < 4; j++)
#pragma unroll
            for (int f = 0; f < 4; f++) acc[i][j][f] = 0.f;

#define PJ_FILL(st, k0, WROW0)                                                \
    do {                                                                      \
        __half* Xs = sh + (st) * PJ_STG;                                      \
        __half* Ws = Xs + 128 * PJ_LD;                                        \
        _Pragma("unroll")                                                     \
        for (int t = 0; t < 4; t++) {                                         \
            int seg = tid + t * 256;                                          \
            int row = seg >> 3, c16 = seg & 7;                                \
            CPA16(su32(Xs + row * PJ_LD + c16 * 8),                           \
                  &g_xh[(size_t)(m0 + row) * E_DIM + (k0) + c16 * 8]);        \
        }                                                                     \
        _Pragma("unroll")                                                     \
        for (int t = 0; t < 4; t++) {                                         \
            int seg = tid + t * 256;                                          \
            int row = seg >> 3, c16 = seg & 7;                                \
            CPA16(su32(Ws + row * PJ_LD + c16 * 8),                           \
                  &g_Wh[(size_t)((WROW0) + row) * E_DIM + (k0) + c16 * 8]);   \
        }                                                                     \
        CP_COMMIT();                                                          \
    } while (0)

    PJ_FILL(0, 0,  E_DIM + n0);
    PJ_FILL(1, 64, E_DIM + n0);

    const int NKT = E_DIM / 64;
    for (int kt = 0; kt < NKT; kt++) {
        const int st = kt % 3;
        if (kt < NKT - 1) { CP_WAIT(1); } else { CP_WAIT(0); }
        __syncthreads();

        const __half* Xs = sh + st * PJ_STG;
        const __half* Ws = Xs + 128 * PJ_LD;

#pragma unroll
        for (int ks = 0; ks < 4; ks++) {
            const int kb = ks * 16;
            unsigned a[4][4];
#pragma unroll
            for (int i = 0; i < 4; i++) {
                int row = warpM * 64 + i * 16 + ((quad & 1) << 3) + rr;
                int col = kb + ((quad >> 1) << 3);
                LDSM_X4(a[i][0], a[i][1], a[i][2], a[i][3],
                        su32(Xs + row * PJ_LD + col));
            }
#pragma unroll
            for (int jj = 0; jj < 2; jj++) {
                int nrow = warpN * 32 + jj * 16 + ((quad >> 1) << 3) + rr;
                int col  = kb + ((quad & 1) << 3);
                unsigned b0, b1, b2, b3;
                LDSM_X4(b0, b1, b2, b3, su32(Ws + nrow * PJ_LD + col));
#pragma unroll
                for (int i = 0; i < 4; i++) {
                    MMA16(acc[i][2 * jj],     a[i], b0, b1);
                    MMA16(acc[i][2 * jj + 1], a[i], b2, b3);
                }
            }
        }

        if (kt + 2 < NKT) PJ_FILL((kt + 2) % 3, (kt + 2) * 64, E_DIM + n0);
    }

    const int which = n0 >> 10;           // 0 -> K, 1 -> V
    const int nbase = n0 & 1023;
    const float* bias = which ? bv : bk;
    __half* C = which ? g_Vh : g_Kh;

#pragma unroll
    for (int j = 0; j < 4; j++) {
        int col = nbase + warpN * 32 + j * 8 + tg * 2;
        float b0 = bias[col], b1 = bias[col + 1];
#pragma unroll
        for (int i = 0; i < 4; i++) {
            int rbase = m0 + warpM * 64 + i * 16;
            *(__half2*)&C[(size_t)(rbase + g) * E_DIM + col] =
                __floats2half2_rn(acc[i][j][0] + b0, acc[i][j][1] + b1);
            *(__half2*)&C[(size_t)(rbase + g + 8) * E_DIM + col] =
                __floats2half2_rn(acc[i][j][2] + b0, acc[i][j][3] + b1);
        }
    }
}

// ---------------------------------------------------------------------------
// kv_kernel: partial T[n,ch] = K[n, ch*1024:+1024]^T @ V[same]  (f32)
// grid (2, 32) = 64 CTAs, 16 inner chunks of 64. Scale deferred to proj_q.
// ---------------------------------------------------------------------------
#define KV_LD 72

__global__ __launch_bounds__(256) void kv_kernel()
{
    const int ch = blockIdx.x;            // 0..1
    const int b  = blockIdx.y;            // 0..31
    const __half* Kg = g_Kh + (size_t)b * SEQ * HD + (size_t)ch * 1024 * HD;
    const __half* Vg = g_Vh + (size_t)b * SEQ * HD + (size_t)ch * 1024 * HD;

    __shared__ __half Ks[2][64 * KV_LD];
    __shared__ __half Vs[2][64 * KV_LD];

    const int tid  = threadIdx.x, lane = tid & 31, warp = tid >> 5;
    const int g = lane >> 2, tg = lane & 3;
    const int quad = lane >> 3, rr = lane & 7;
    const int mh = (warp >> 2) * 32;
    const int nb = (warp & 3) * 16;

    float accT[2][2][4];
#pragma unroll
    for (int mt = 0; mt < 2; mt++)
#pragma unroll
        for (int jn = 0; jn < 2; jn++)
#pragma unroll
            for (int f = 0; f < 4; f++) accT[mt][jn][f] = 0.f;

#define KV2_ISSUE(buf, k0)                                                    \
    do {                                                                      \
        _Pragma("unroll")                                                     \
        for (int t = 0; t < 2; t++) {                                         \
            int seg = tid + t * 256;                                          \
            int row = seg >> 3, s8 = seg & 7;                                 \
            CPA16(su32(&Ks[buf][row * KV_LD + s8 * 8]),                       \
                  &Kg[(size_t)((k0) + row) * HD + s8 * 8]);                   \
            CPA16(su32(&Vs[buf][row * KV_LD + s8 * 8]),                       \
                  &Vg[(size_t)((k0) + row) * HD + s8 * 8]);                   \
        }                                                                     \
        CP_COMMIT();                                                          \
    } while (0)

    KV2_ISSUE(0, 0);

    for (int c = 0; c < 16; c++) {
        int buf = c & 1;
        __syncthreads();
        if (c < 15) { KV2_ISSUE(buf ^ 1, (c + 1) * 64); CP_WAIT(1); }
        else        { CP_WAIT(0); }
        __syncthreads();

#pragma unroll
        for (int ks = 0; ks < 4; ks++) {
            const int sb = ks * 16;
            unsigned a[2][4];
#pragma unroll
            for (int mt = 0; mt < 2; mt++) {
                int row = sb + ((quad >> 1) << 3) + rr;
                int col = mh + mt * 16 + ((quad & 1) << 3);
                LDSM_X4T(a[mt][0], a[mt][1], a[mt][2], a[mt][3],
                         su32(&Ks[buf][row * KV_LD + col]));
            }
            int vrow = sb + ((quad & 1) << 3) + rr;
            int vcol = nb + ((quad >> 1) << 3);
            unsigned v0, v1, v2, v3;
            LDSM_X4T(v0, v1, v2, v3, su32(&Vs[buf][vrow * KV_LD + vcol]));
#pragma unroll
            for (int mt = 0; mt < 2; mt++) {
                MMA16(accT[mt][0], a[mt], v0, v1);
                MMA16(accT[mt][1], a[mt], v2, v3);
            }
        }
    }

    float* Tp = g_Tp + ((size_t)(b * 2 + ch)) * HD * HD;
#pragma unroll
    for (int mt = 0; mt < 2; mt++) {
        int dk0 = mh + mt * 16;
#pragma unroll
        for (int jn = 0; jn < 2; jn++) {
            int dv = nb + jn * 8 + tg * 2;
            *(float2*)&Tp[(dk0 + g) * HD + dv] =
                make_float2(accT[mt][jn][0], accT[mt][jn][1]);
            *(float2*)&Tp[(dk0 + g + 8) * HD + dv] =
                make_float2(accT[mt][jn][2], accT[mt][jn][3]);
        }
    }
}

// ---------------------------------------------------------------------------
// proj_q: q tile = X @ Wq^T + bq (128x128 = 2 heads), then FUSED epilogue:
//   T[n] = 0.125*(Tp[n,0]+Tp[n,1]) reduced inline from L2,
//   out row R = 16*m + h:  out[R] = q64(m,h) @ T[n],  n = blockIdx.y.
// grid (8, 32). g_Qh never materialized.
// ---------------------------------------------------------------------------
#define QST_LD 136

__global__ __launch_bounds__(256, 2) void proj_q_kernel(
    const float* __restrict__ bq, float* __restrict__ out)
{
    extern __shared__ __half sh[];

    const int tid  = threadIdx.x, lane = tid & 31;
    const int warp = tid >> 5, warpM = warp >> 2, warpN = warp & 3;
    const int g = lane >> 2, tg = lane & 3;
    const int quad = lane >> 3, rr = lane & 7;
    const int m0 = blockIdx.y * 128;
    const int n0 = blockIdx.x * 128;      // q cols: heads h0, h0+1
    const int h0 = n0 >> 6;

    float acc[4][4][4];
#pragma unroll
    for (int i = 0; i < 4; i++)
#pragma unroll
        for (int j = 0; j < 4; j++)
#pragma unroll
            for (int f = 0; f < 4; f++) acc[i][j][f] = 0.f;

    PJ_FILL(0, 0,  n0);
    PJ_FILL(1, 64, n0);

    const int NKT = E_DIM / 64;
    for (int kt = 0; kt < NKT; kt++) {
        const int st = kt % 3;
        if (kt < NKT - 1) { CP_WAIT(1); } else { CP_WAIT(0); }
        __syncthreads();

        const __half* Xs = sh + st * PJ_STG;
        const __half* Ws = Xs + 128 * PJ_LD;

#pragma unroll
        for (int ks = 0; ks < 4; ks++) {
            const int kb = ks * 16;
            unsigned a[4][4];
#pragma unroll
            for (int i = 0; i < 4; i++) {
                int row = warpM * 64 + i * 16 + ((quad & 1) << 3) + rr;
                int col = kb + ((quad >> 1) << 3);
                LDSM_X4(a[i][0], a[i][1], a[i][2], a[i][3],
                        su32(Xs + row * PJ_LD + col));
            }
#pragma unroll
            for (int jj = 0; jj < 2; jj++) {
                int nrow = warpN * 32 + jj * 16 + ((quad >> 1) << 3) + rr;
                int col  = kb + ((quad & 1) << 3);
                unsigned b0, b1, b2, b3;
                LDSM_X4(b0, b1, b2, b3, su32(Ws + nrow * PJ_LD + col));
#pragma unroll
                for (int i = 0; i < 4; i++) {
                    MMA16(acc[i][2 * jj],     a[i], b0, b1);
                    MMA16(acc[i][2 * jj + 1], a[i], b2, b3);
                }
            }
        }

        if (kt + 2 < NKT) PJ_FILL((kt + 2) % 3, (kt + 2) * 64, n0);
    }

    // ---- Fused epilogue ----
    __syncthreads();                       // all warps done with stage buffers
    __half* Qst = sh;                      // [128][QST_LD]
    __half* Tst = sh + 128 * QST_LD;       // [64][72]

    // Inline T reduce from the 2 f32 partials (L2-hot), x0.125 -> f16 smem.
    {
        const float4* P0 = (const float4*)(g_Tp + (size_t)blockIdx.y * 2 * HD * HD);
        const float4* P1 = P0 + 1024;
#pragma unroll
        for (int t = 0; t < 2; t++) {
            int slot = tid + t * 256;        // 0..511; each = 2 float4
            float4 a0 = P0[2 * slot],     a1 = P1[2 * slot];
            float4 b0 = P0[2 * slot + 1], b1 = P1[2 * slot + 1];
            int row = slot >> 3, c8 = (slot & 7) * 8;
            *(__half2*)&Tst[row * 72 + c8] =
                __floats2half2_rn((a0.x + a1.x) * 0.125f, (a0.y + a1.y) * 0.125f);
            *(__half2*)&Tst[row * 72 + c8 + 2] =
                __floats2half2_rn((a0.z + a1.z) * 0.125f, (a0.w + a1.w) * 0.125f);
            *(__half2*)&Tst[row * 72 + c8 + 4] =
                __floats2half2_rn((b0.x + b1.x) * 0.125f, (b0.y + b1.y) * 0.125f);
            *(__half2*)&Tst[row * 72 + c8 + 6] =
                __floats2half2_rn((b0.z + b1.z) * 0.125f, (b0.w + b1.w) * 0.125f);
        }
    }

    // stage q tile (+bq) to Qst
#pragma unroll
    for (int j = 0; j < 4; j++) {
        int col = warpN * 32 + j * 8 + tg * 2;          // 0..127 local
        float b0 = bq[n0 + col], b1 = bq[n0 + col + 1];
#pragma unroll
        for (int i = 0; i < 4; i++) {
            int rl = warpM * 64 + i * 16;
            *(__half2*)&Qst[(rl + g) * QST_LD + col] =
                __floats2half2_rn(acc[i][j][0] + b0, acc[i][j][1] + b1);
            *(__half2*)&Qst[(rl + g + 8) * QST_LD + col] =
                __floats2half2_rn(acc[i][j][2] + b0, acc[i][j][3] + b1);
        }
    }
    __syncthreads();

    // warp w: head hl = w>>2, rows mb = (w&3)*32 .. +32
    const int hl = warp >> 2;
    const int mb = (warp & 3) * 32;

    float accF[2][4][2][4];
#pragma unroll
    for (int i = 0; i < 2; i++)
#pragma unroll
        for (int jj = 0; jj < 4; jj++)
#pragma unroll
            for (int jn = 0; jn < 2; jn++)
#pragma unroll
                for (int f = 0; f < 4; f++) accF[i][jj][jn][f] = 0.f;

#pragma unroll
    for (int k = 0; k < 4; k++) {
        const int kb = k * 16;
        unsigned a[2][4];
#pragma unroll
        for (int i = 0; i < 2; i++) {
            int row = mb + i * 16 + ((quad & 1) << 3) + rr;
            int col = hl * 64 + kb + ((quad >> 1) << 3);
            LDSM_X4(a[i][0], a[i][1], a[i][2], a[i][3],
                    su32(Qst + row * QST_LD + col));
        }
#pragma unroll
        for (int jj = 0; jj < 4; jj++) {
            int trow = kb + ((quad & 1) << 3) + rr;
            int tcol = jj * 16 + ((quad >> 1) << 3);
            unsigned v0, v1, v2, v3;
            LDSM_X4T(v0, v1, v2, v3, su32(Tst + trow * 72 + tcol));
#pragma unroll
            for (int i = 0; i < 2; i++) {
                MMA16(accF[i][jj][0], a[i], v0, v1);
                MMA16(accF[i][jj][1], a[i], v2, v3);
            }
        }
    }

    // store: out[(16*(m0+mloc) + h0+hl)*64 + d]
#pragma unroll
    for (int i = 0; i < 2; i++) {
        int mA = m0 + mb + i * 16 + g;
        int mB = mA + 8;
        size_t RA = (size_t)(16 * mA + h0 + hl) * HD;
        size_t RB = (size_t)(16 * mB + h0 + hl) * HD;
#pragma unroll
        for (int jj = 0; jj < 4; jj++) {
#pragma unroll
            for (int jn = 0; jn < 2; jn++) {
                int d = jj * 16 + jn * 8 + tg * 2;
                *(float2*)&out[RA + d] =
                    make_float2(accF[i][jj][jn][0], accF[i][jj][jn][1]);
                *(float2*)&out[RB + d] =
                    make_float2(accF[i][jj][jn][2], accF[i][jj][jn][3]);
            }
        }
    }
}

// ---------------------------------------------------------------------------
extern "C" void kernel_launch(void* const* d_in, const int* in_sizes, int n_in,
                              void* d_out, int out_size)
{
    const float* x  = (const float*)d_in[0];
    const float* Wq = (const float*)d_in[1];
    const float* bq = (const float*)d_in[2];
    const float* Wk = (const float*)d_in[3];
    const float* bk = (const float*)d_in[4];
    const float* Wv = (const float*)d_in[5];
    const float* bv = (const float*)d_in[6];
    float* out = (float*)d_out;

    cudaFuncSetAttribute(proj_kv_kernel,
                         cudaFuncAttributeMaxDynamicSharedMemorySize, PJ_SMEM);
    cudaFuncSetAttribute(proj_q_kernel,
                         cudaFuncAttributeMaxDynamicSharedMemorySize, PJ_SMEM);

    cvt_kernel<<<(CVT_TOT / 2 + 255) / 256, 256>>>(x, Wq, Wk, Wv);

    proj_kv_kernel<<<dim3(2 * E_DIM / 128, M_TOT / 128), 256, PJ_SMEM>>>(bk, bv);

    kv_kernel<<<dim3(2, NBATCH), 256>>>();

    proj_q_kernel<<<dim3(E_DIM / 128, M_TOT / 128), 256, PJ_SMEM>>>(bq, out);
}

// round 11
// speedup vs baseline: 1.0210x; 1.0184x over previous
#include <cuda_runtime.h>
#include <cuda_fp16.h>

#define E_DIM   1024
#define M_TOT   4096
#define SEQ     2048
#define NBATCH  32
#define HD      64

// scratch
__device__ __half g_xh[M_TOT * E_DIM];
__device__ __half g_Wh[3 * E_DIM * E_DIM];    // Wq | Wk | Wv stacked [3072,1024]
__device__ __half g_Kh[M_TOT * E_DIM];
__device__ __half g_Vh[M_TOT * E_DIM];
__device__ float  g_Tp[NBATCH * 8 * HD * HD]; // 8 partials of K^T V per n
__device__ int    g_cnt[NBATCH];              // producer counters

__device__ __forceinline__ unsigned su32(const void* p) {
    return (unsigned)__cvta_generic_to_shared(p);
}
#define CPA16(d, s) \
    asm volatile("cp.async.cg.shared.global [%0],[%1],16;" :: "r"(d), "l"(s))
#define CP_COMMIT() asm volatile("cp.async.commit_group;")
#define CP_WAIT(n)  asm volatile("cp.async.wait_group %0;" :: "n"(n))

#define LDSM_X4(r0, r1, r2, r3, p) \
    asm volatile("ldmatrix.sync.aligned.m8n8.x4.shared.b16 {%0,%1,%2,%3},[%4];" \
                 : "=r"(r0), "=r"(r1), "=r"(r2), "=r"(r3) : "r"(p))
#define LDSM_X4T(r0, r1, r2, r3, p) \
    asm volatile("ldmatrix.sync.aligned.m8n8.x4.trans.shared.b16 {%0,%1,%2,%3},[%4];" \
                 : "=r"(r0), "=r"(r1), "=r"(r2), "=r"(r3) : "r"(p))

#define MMA16(c, a, b0_, b1_) \
    asm volatile("mma.sync.aligned.m16n8k16.row.col.f32.f16.f16.f32 " \
                 "{%0,%1,%2,%3},{%4,%5,%6,%7},{%8,%9},{%0,%1,%2,%3};" \
                 : "+f"((c)[0]), "+f"((c)[1]), "+f"((c)[2]), "+f"((c)[3]) \
                 : "r"((a)[0]), "r"((a)[1]), "r"((a)[2]), "r"((a)[3]), \
                   "r"(b0_), "r"(b1_))

// ---------------------------------------------------------------------------
// cvt: f32 -> f16 for x, Wq, Wk, Wv (2 float4/thread). Also resets g_cnt.
// ---------------------------------------------------------------------------
#define CVT_NX ((M_TOT * E_DIM) / 4)
#define CVT_NW ((E_DIM * E_DIM) / 4)
#define CVT_TOT (CVT_NX + 3 * CVT_NW)

__device__ __forceinline__ void cvt_one(const float* __restrict__ x,
                                        const float* __restrict__ wq,
                                        const float* __restrict__ wk,
                                        const float* __restrict__ wv, int i)
{
    const float* s; __half* d; int off;
    if (i < CVT_NX)                   { s = x;  d = g_xh;                     off = i; }
    else if (i < CVT_NX + CVT_NW)     { s = wq; d = g_Wh;                     off = i - CVT_NX; }
    else if (i < CVT_NX + 2 * CVT_NW) { s = wk; d = g_Wh + E_DIM * E_DIM;     off = i - CVT_NX - CVT_NW; }
    else                              { s = wv; d = g_Wh + 2 * E_DIM * E_DIM; off = i - CVT_NX - 2 * CVT_NW; }
    float4 v = ((const float4*)s)[off];
    ((__half2*)d)[2 * off]     = __floats2half2_rn(v.x, v.y);
    ((__half2*)d)[2 * off + 1] = __floats2half2_rn(v.z, v.w);
}

__global__ void cvt_kernel(const float* __restrict__ x,
                           const float* __restrict__ wq,
                           const float* __restrict__ wk,
                           const float* __restrict__ wv)
{
    if (blockIdx.x == 0 && threadIdx.x < NBATCH) g_cnt[threadIdx.x] = 0;
    int i = (blockIdx.x * 256 + threadIdx.x) * 2;
    if (i + 1 >= CVT_TOT) { if (i < CVT_TOT) cvt_one(x, wq, wk, wv, i); return; }
    cvt_one(x, wq, wk, wv, i);
    cvt_one(x, wq, wk, wv, i + 1);
}

// ---------------------------------------------------------------------------
// proj_kv: C[4096,2048] = X @ [Wk;Wv]^T + bias  -> g_Kh / g_Vh (f16)
// CTA 128x128, BK=64, 3-stage cp.async, 8 warps (2x4). grid (16, 32).
// ---------------------------------------------------------------------------
#define PJ_LD   72
#define PJ_STG  ((128 + 128) * PJ_LD)
#define PJ_SMEM (3 * PJ_STG * (int)sizeof(__half))   // 110592 B

__global__ __launch_bounds__(256, 2) void proj_kv_kernel(
    const float* __restrict__ bk, const float* __restrict__ bv)
{
    extern __shared__ __half sh[];

    const int tid  = threadIdx.x, lane = tid & 31;
    const int warp = tid >> 5, warpM = warp >> 2, warpN = warp & 3;
    const int g = lane >> 2, tg = lane & 3;
    const int quad = lane >> 3, rr = lane & 7;
    const int m0 = blockIdx.y * 128;
    const int n0 = blockIdx.x * 128;      // 0..2047 over Wk|Wv

    float acc[4][4][4];
#pragma unroll
    for (int i = 0; i < 4; i++)
#pragma unroll
        for (int j = 0; j < 4; j++)
#pragma unroll
            for (int f = 0; f < 4; f++) acc[i][j][f] = 0.f;

#define PJ_FILL(st, k0, WROW0)                                                \
    do {                                                                      \
        __half* Xs = sh + (st) * PJ_STG;                                      \
        __half* Ws = Xs + 128 * PJ_LD;                                        \
        _Pragma("unroll")                                                     \
        for (int t = 0; t < 4; t++) {                                         \
            int seg = tid + t * 256;                                          \
            int row = seg >> 3, c16 = seg & 7;                                \
            CPA16(su32(Xs + row * PJ_LD + c16 * 8),                           \
                  &g_xh[(size_t)(m0 + row) * E_DIM + (k0) + c16 * 8]);        \
        }                                                                     \
        _Pragma("unroll")                                                     \
        for (int t = 0; t < 4; t++) {                                         \
            int seg = tid + t * 256;                                          \
            int row = seg >> 3, c16 = seg & 7;                                \
            CPA16(su32(Ws + row * PJ_LD + c16 * 8),                           \
                  &g_Wh[(size_t)((WROW0) + row) * E_DIM + (k0) + c16 * 8]);   \
        }                                                                     \
        CP_COMMIT();                                                          \
    } while (0)

    PJ_FILL(0, 0,  E_DIM + n0);
    PJ_FILL(1, 64, E_DIM + n0);

    const int NKT = E_DIM / 64;
    for (int kt = 0; kt < NKT; kt++) {
        const int st = kt % 3;
        if (kt < NKT - 1) { CP_WAIT(1); } else { CP_WAIT(0); }
        __syncthreads();

        const __half* Xs = sh + st * PJ_STG;
        const __half* Ws = Xs + 128 * PJ_LD;

#pragma unroll
        for (int ks = 0; ks < 4; ks++) {
            const int kb = ks * 16;
            unsigned a[4][4];
#pragma unroll
            for (int i = 0; i < 4; i++) {
                int row = warpM * 64 + i * 16 + ((quad & 1) << 3) + rr;
                int col = kb + ((quad >> 1) << 3);
                LDSM_X4(a[i][0], a[i][1], a[i][2], a[i][3],
                        su32(Xs + row * PJ_LD + col));
            }
#pragma unroll
            for (int jj = 0; jj < 2; jj++) {
                int nrow = warpN * 32 + jj * 16 + ((quad >> 1) << 3) + rr;
                int col  = kb + ((quad & 1) << 3);
                unsigned b0, b1, b2, b3;
                LDSM_X4(b0, b1, b2, b3, su32(Ws + nrow * PJ_LD + col));
#pragma unroll
                for (int i = 0; i < 4; i++) {
                    MMA16(acc[i][2 * jj],     a[i], b0, b1);
                    MMA16(acc[i][2 * jj + 1], a[i], b2, b3);
                }
            }
        }

        if (kt + 2 < NKT) PJ_FILL((kt + 2) % 3, (kt + 2) * 64, E_DIM + n0);
    }

    const int which = n0 >> 10;           // 0 -> K, 1 -> V
    const int nbase = n0 & 1023;
    const float* bias = which ? bv : bk;
    __half* C = which ? g_Vh : g_Kh;

#pragma unroll
    for (int j = 0; j < 4; j++) {
        int col = nbase + warpN * 32 + j * 8 + tg * 2;
        float b0 = bias[col], b1 = bias[col + 1];
#pragma unroll
        for (int i = 0; i < 4; i++) {
            int rbase = m0 + warpM * 64 + i * 16;
            *(__half2*)&C[(size_t)(rbase + g) * E_DIM + col] =
                __floats2half2_rn(acc[i][j][0] + b0, acc[i][j][1] + b1);
            *(__half2*)&C[(size_t)(rbase + g + 8) * E_DIM + col] =
                __floats2half2_rn(acc[i][j][2] + b0, acc[i][j][3] + b1);
        }
    }
}

// ---------------------------------------------------------------------------
// proj_q: fused producer/consumer kernel. grid (8, 32), all 256 CTAs
// co-resident (occ=2 guaranteed by launch_bounds + smem).
// Phase 0 (producer): partial T over s'-rows [ch*256,+256) of batch n;
//                     store f32 partial; fence; count++.
// Phase 1: q tile = X @ Wq^T (128x128 = 2 heads), 3-stage pipeline.
// Phase 2 (consumer): spin cnt[n]==8; reduce 8 partials *0.125 -> f16 smem;
//                     out rows R=16m+h: out[R] = q64(m,h) @ T[n].
// ---------------------------------------------------------------------------
#define QST_LD 136
#define KV_LD  72

__global__ __launch_bounds__(256, 2) void proj_q_kernel(
    const float* __restrict__ bq, float* __restrict__ out)
{
    extern __shared__ __half sh[];

    const int tid  = threadIdx.x, lane = tid & 31;
    const int warp = tid >> 5, warpM = warp >> 2, warpN = warp & 3;
    const int g = lane >> 2, tg = lane & 3;
    const int quad = lane >> 3, rr = lane & 7;
    const int ch = blockIdx.x;            // partial chunk AND n-tile (h0 = 2*ch)
    const int n  = blockIdx.y;            // batch n AND m-tile (m0 = 128*n)
    const int m0 = n * 128;
    const int n0 = ch * 128;
    const int h0 = n0 >> 6;

    // ================= Phase 0: producer — partial T[n][ch] ================
    {
        const __half* Kg = g_Kh + (size_t)n * SEQ * HD + (size_t)ch * 256 * HD;
        const __half* Vg = g_Vh + (size_t)n * SEQ * HD + (size_t)ch * 256 * HD;
        __half* Ksb = sh;                          // [2][64*KV_LD]
        __half* Vsb = sh + 2 * 64 * KV_LD;         // [2][64*KV_LD]

        const int mh = (warp >> 2) * 32;
        const int nb = (warp & 3) * 16;

        float accT[2][2][4];
#pragma unroll
        for (int mt = 0; mt < 2; mt++)
#pragma unroll
            for (int jn = 0; jn < 2; jn++)
#pragma unroll
                for (int f = 0; f < 4; f++) accT[mt][jn][f] = 0.f;

#define KVP_ISSUE(buf, k0)                                                    \
        do {                                                                  \
            _Pragma("unroll")                                                 \
            for (int t = 0; t < 2; t++) {                                     \
                int seg = tid + t * 256;                                      \
                int row = seg >> 3, s8 = seg & 7;                             \
                CPA16(su32(Ksb + (buf) * 64 * KV_LD + row * KV_LD + s8 * 8),  \
                      &Kg[(size_t)((k0) + row) * HD + s8 * 8]);               \
                CPA16(su32(Vsb + (buf) * 64 * KV_LD + row * KV_LD + s8 * 8),  \
                      &Vg[(size_t)((k0) + row) * HD + s8 * 8]);               \
            }                                                                 \
            CP_COMMIT();                                                      \
        } while (0)

        KVP_ISSUE(0, 0);

        for (int c = 0; c < 4; c++) {
            int buf = c & 1;
            __syncthreads();
            if (c < 3) { KVP_ISSUE(buf ^ 1, (c + 1) * 64); CP_WAIT(1); }
            else       { CP_WAIT(0); }
            __syncthreads();

            const __half* Ksx = Ksb + buf * 64 * KV_LD;
            const __half* Vsx = Vsb + buf * 64 * KV_LD;
#pragma unroll
            for (int ks = 0; ks < 4; ks++) {
                const int sb = ks * 16;
                unsigned a[2][4];
#pragma unroll
                for (int mt = 0; mt < 2; mt++) {
                    int row = sb + ((quad >> 1) << 3) + rr;
                    int col = mh + mt * 16 + ((quad & 1) << 3);
                    LDSM_X4T(a[mt][0], a[mt][1], a[mt][2], a[mt][3],
                             su32(Ksx + row * KV_LD + col));
                }
                int vrow = sb + ((quad & 1) << 3) + rr;
                int vcol = nb + ((quad >> 1) << 3);
                unsigned v0, v1, v2, v3;
                LDSM_X4T(v0, v1, v2, v3, su32(Vsx + vrow * KV_LD + vcol));
#pragma unroll
                for (int mt = 0; mt < 2; mt++) {
                    MMA16(accT[mt][0], a[mt], v0, v1);
                    MMA16(accT[mt][1], a[mt], v2, v3);
                }
            }
        }

        float* Tp = g_Tp + ((size_t)(n * 8 + ch)) * HD * HD;
#pragma unroll
        for (int mt = 0; mt < 2; mt++) {
            int dk0 = mh + mt * 16;
#pragma unroll
            for (int jn = 0; jn < 2; jn++) {
                int dv = nb + jn * 8 + tg * 2;
                *(float2*)&Tp[(dk0 + g) * HD + dv] =
                    make_float2(accT[mt][jn][0], accT[mt][jn][1]);
                *(float2*)&Tp[(dk0 + g + 8) * HD + dv] =
                    make_float2(accT[mt][jn][2], accT[mt][jn][3]);
            }
        }
        __threadfence();
        __syncthreads();
        if (tid == 0) atomicAdd(&g_cnt[n], 1);
        __syncthreads();
    }

    // ================= Phase 1: q tile GEMM =================
    float acc[4][4][4];
#pragma unroll
    for (int i = 0; i < 4; i++)
#pragma unroll
        for (int j = 0; j < 4; j++)
#pragma unroll
            for (int f = 0; f < 4; f++) acc[i][j][f] = 0.f;

    PJ_FILL(0, 0,  n0);
    PJ_FILL(1, 64, n0);

    const int NKT = E_DIM / 64;
    for (int kt = 0; kt < NKT; kt++) {
        const int st = kt % 3;
        if (kt < NKT - 1) { CP_WAIT(1); } else { CP_WAIT(0); }
        __syncthreads();

        const __half* Xs = sh + st * PJ_STG;
        const __half* Ws = Xs + 128 * PJ_LD;

#pragma unroll
        for (int ks = 0; ks < 4; ks++) {
            const int kb = ks * 16;
            unsigned a[4][4];
#pragma unroll
            for (int i = 0; i < 4; i++) {
                int row = warpM * 64 + i * 16 + ((quad & 1) << 3) + rr;
                int col = kb + ((quad >> 1) << 3);
                LDSM_X4(a[i][0], a[i][1], a[i][2], a[i][3],
                        su32(Xs + row * PJ_LD + col));
            }
#pragma unroll
            for (int jj = 0; jj < 2; jj++) {
                int nrow = warpN * 32 + jj * 16 + ((quad >> 1) << 3) + rr;
                int col  = kb + ((quad & 1) << 3);
                unsigned b0, b1, b2, b3;
                LDSM_X4(b0, b1, b2, b3, su32(Ws + nrow * PJ_LD + col));
#pragma unroll
                for (int i = 0; i < 4; i++) {
                    MMA16(acc[i][2 * jj],     a[i], b0, b1);
                    MMA16(acc[i][2 * jj + 1], a[i], b2, b3);
                }
            }
        }

        if (kt + 2 < NKT) PJ_FILL((kt + 2) % 3, (kt + 2) * 64, n0);
    }

    // ================= Phase 2: consumer — fused epilogue =================
    __syncthreads();                       // stage buffers free
    __half* Qst = sh;                      // [128][QST_LD]
    __half* Tst = sh + 128 * QST_LD;       // [64][72]

    // stage q tile (+bq) to Qst first (overlaps any residual spin)
#pragma unroll
    for (int j = 0; j < 4; j++) {
        int col = warpN * 32 + j * 8 + tg * 2;          // 0..127 local
        float b0 = bq[n0 + col], b1 = bq[n0 + col + 1];
#pragma unroll
        for (int i = 0; i < 4; i++) {
            int rl = warpM * 64 + i * 16;
            *(__half2*)&Qst[(rl + g) * QST_LD + col] =
                __floats2half2_rn(acc[i][j][0] + b0, acc[i][j][1] + b1);
            *(__half2*)&Qst[(rl + g + 8) * QST_LD + col] =
                __floats2half2_rn(acc[i][j][2] + b0, acc[i][j][3] + b1);
        }
    }

    // spin until all 8 partials for this n are published
    if (tid == 0) {
        while (atomicAdd(&g_cnt[n], 0) < 8) { }
    }
    __syncthreads();
    __threadfence();

    // reduce 8 partials -> Tst (f16, x0.125)
    {
        const float4* P = (const float4*)(g_Tp + (size_t)n * 8 * HD * HD);
#pragma unroll
        for (int t = 0; t < 4; t++) {
            int slot = tid + t * 256;        // 0..1023 float4 slots
            float4 s0 = P[slot];
#pragma unroll
            for (int p = 1; p < 8; p++) {
                float4 q = P[p * 1024 + slot];
                s0.x += q.x; s0.y += q.y; s0.z += q.z; s0.w += q.w;
            }
            int row = slot >> 4, col = (slot & 15) * 4;
            *(__half2*)&Tst[row * 72 + col] =
                __floats2half2_rn(s0.x * 0.125f, s0.y * 0.125f);
            *(__half2*)&Tst[row * 72 + col + 2] =
                __floats2half2_rn(s0.z * 0.125f, s0.w * 0.125f);
        }
    }
    __syncthreads();

    // warp w: head hl = w>>2, rows mb = (w&3)*32 .. +32
    const int hl = warp >> 2;
    const int mb = (warp & 3) * 32;

    float accF[2][4][2][4];
#pragma unroll
    for (int i = 0; i < 2; i++)
#pragma unroll
        for (int jj = 0; jj < 4; jj++)
#pragma unroll
            for (int jn = 0; jn < 2; jn++)
#pragma unroll
                for (int f = 0; f < 4; f++) accF[i][jj][jn][f] = 0.f;

#pragma unroll
    for (int k = 0; k < 4; k++) {
        const int kb = k * 16;
        unsigned a[2][4];
#pragma unroll
        for (int i = 0; i < 2; i++) {
            int row = mb + i * 16 + ((quad & 1) << 3) + rr;
            int col = hl * 64 + kb + ((quad >> 1) << 3);
            LDSM_X4(a[i][0], a[i][1], a[i][2], a[i][3],
                    su32(Qst + row * QST_LD + col));
        }
#pragma unroll
        for (int jj = 0; jj < 4; jj++) {
            int trow = kb + ((quad & 1) << 3) + rr;
            int tcol = jj * 16 + ((quad >> 1) << 3);
            unsigned v0, v1, v2, v3;
            LDSM_X4T(v0, v1, v2, v3, su32(Tst + trow * 72 + tcol));
#pragma unroll
            for (int i = 0; i < 2; i++) {
                MMA16(accF[i][jj][0], a[i], v0, v1);
                MMA16(accF[i][jj][1], a[i], v2, v3);
            }
        }
    }

    // store: out[(16*(m0+mloc) + h0+hl)*64 + d]
#pragma unroll
    for (int i = 0; i < 2; i++) {
        int mA = m0 + mb + i * 16 + g;
        int mB = mA + 8;
        size_t RA = (size_t)(16 * mA + h0 + hl) * HD;
        size_t RB = (size_t)(16 * mB + h0 + hl) * HD;
#pragma unroll
        for (int jj = 0; jj < 4; jj++) {
#pragma unroll
            for (int jn = 0; jn < 2; jn++) {
                int d = jj * 16 + jn * 8 + tg * 2;
                *(float2*)&out[RA + d] =
                    make_float2(accF[i][jj][jn][0], accF[i][jj][jn][1]);
                *(float2*)&out[RB + d] =
                    make_float2(accF[i][jj][jn][2], accF[i][jj][jn][3]);
            }
        }
    }
}

// ---------------------------------------------------------------------------
extern "C" void kernel_launch(void* const* d_in, const int* in_sizes, int n_in,
                              void* d_out, int out_size)
{
    const float* x  = (const float*)d_in[0];
    const float* Wq = (const float*)d_in[1];
    const float* bq = (const float*)d_in[2];
    const float* Wk = (const float*)d_in[3];
    const float* bk = (const float*)d_in[4];
    const float* Wv = (const float*)d_in[5];
    const float* bv = (const float*)d_in[6];
    float* out = (float*)d_out;

    cudaFuncSetAttribute(proj_kv_kernel,
                         cudaFuncAttributeMaxDynamicSharedMemorySize, PJ_SMEM);
    cudaFuncSetAttribute(proj_q_kernel,
                         cudaFuncAttributeMaxDynamicSharedMemorySize, PJ_SMEM);

    cvt_kernel<<<(CVT_TOT / 2 + 255) / 256, 256>>>(x, Wq, Wk, Wv);

    proj_kv_kernel<<<dim3(2 * E_DIM / 128, M_TOT / 128), 256, PJ_SMEM>>>(bk, bv);

    proj_q_kernel<<<dim3(E_DIM / 128, M_TOT / 128), 256, PJ_SMEM>>>(bq, out);
}